// round 1
// baseline (speedup 1.0000x reference)
#include <cuda_runtime.h>
#include <cstddef>

#define NUM_NODES 50000
#define HID 64
#define IN_DIM 512

// Scratch (no allocation allowed -> __device__ globals)
__device__ float g_deg[NUM_NODES];              // deg -> dinv (in place)
__device__ float g_bufA[NUM_NODES * HID];       // hn1, then h2 (relu output), ...
__device__ float g_bufB[NUM_NODES * HID];       // agg1, then hn2

// ---------------------------------------------------------------------------
// degree / normalization
// ---------------------------------------------------------------------------
__global__ void k_init_deg(float* deg, int n) {
    int i = blockIdx.x * blockDim.x + threadIdx.x;
    if (i < n) deg[i] = 1.0f;  // self-loop
}

__global__ void k_accum_deg(const int* __restrict__ dst, float* deg, int E) {
    int e = blockIdx.x * blockDim.x + threadIdx.x;
    if (e < E) atomicAdd(&deg[dst[e]], 1.0f);
}

__global__ void k_rsqrt(float* deg, int n) {
    int i = blockIdx.x * blockDim.x + threadIdx.x;
    if (i < n) deg[i] = rsqrtf(deg[i]);  // deg >= 1 always (self-loop)
}

// ---------------------------------------------------------------------------
// GEMM with epilogue: hn[row] = (X @ W)[row] * dinv[row]; agg init = hn.
// BM=128, BN=64(full), BK=16, 128 threads, 8x8 register tile per thread.
// ---------------------------------------------------------------------------
template <int K>
__global__ void __launch_bounds__(128)
k_gemm_hn(const float* __restrict__ X, const float* __restrict__ W,
          const float* __restrict__ dinv,
          float* __restrict__ hn, float* __restrict__ agg, int M) {
    __shared__ float xs[16][128];  // transposed X tile: xs[k][row]
    __shared__ float ws[16][64];   // W tile: ws[k][col]

    const int tid = threadIdx.x;        // 0..127
    const int m0  = blockIdx.x * 128;
    const int tm  = tid >> 3;           // 0..15 (row group)
    const int tn  = tid & 7;            // 0..7  (col group)

    float acc[8][8];
#pragma unroll
    for (int i = 0; i < 8; i++)
#pragma unroll
        for (int j = 0; j < 8; j++) acc[i][j] = 0.0f;

    for (int k0 = 0; k0 < K; k0 += 16) {
        // --- load X tile: each thread owns one row, 16 k-values (4 x float4)
        {
            int row = m0 + tid;
#pragma unroll
            for (int i = 0; i < 4; i++) {
                float4 v = make_float4(0.f, 0.f, 0.f, 0.f);
                if (row < M)
                    v = *(const float4*)(X + (size_t)row * K + k0 + i * 4);
                xs[i * 4 + 0][tid] = v.x;
                xs[i * 4 + 1][tid] = v.y;
                xs[i * 4 + 2][tid] = v.z;
                xs[i * 4 + 3][tid] = v.w;
            }
        }
        // --- load W tile: 16x64 floats, 2 float4 per thread
        {
            int kr = tid >> 4;            // 0..7
            int cc = (tid & 15) * 4;      // 0..60
#pragma unroll
            for (int i = 0; i < 2; i++) {
                float4 v = *(const float4*)(W + (size_t)(k0 + kr + i * 8) * 64 + cc);
                *(float4*)(&ws[kr + i * 8][cc]) = v;
            }
        }
        __syncthreads();

#pragma unroll
        for (int kk = 0; kk < 16; kk++) {
            float a[8], b[8];
            *(float4*)(a)     = *(const float4*)(&xs[kk][tm * 8]);
            *(float4*)(a + 4) = *(const float4*)(&xs[kk][tm * 8 + 4]);
            *(float4*)(b)     = *(const float4*)(&ws[kk][tn * 8]);
            *(float4*)(b + 4) = *(const float4*)(&ws[kk][tn * 8 + 4]);
#pragma unroll
            for (int i = 0; i < 8; i++)
#pragma unroll
                for (int j = 0; j < 8; j++)
                    acc[i][j] += a[i] * b[j];
        }
        __syncthreads();
    }

    // --- epilogue: scale by dinv[row], write hn and agg(init = self-loop term)
#pragma unroll
    for (int i = 0; i < 8; i++) {
        int row = m0 + tm * 8 + i;
        if (row >= M) break;
        float s = dinv[row];
#pragma unroll
        for (int jj = 0; jj < 2; jj++) {
            float4 v;
            v.x = acc[i][jj * 4 + 0] * s;
            v.y = acc[i][jj * 4 + 1] * s;
            v.z = acc[i][jj * 4 + 2] * s;
            v.w = acc[i][jj * 4 + 3] * s;
            size_t off = (size_t)row * 64 + tn * 8 + jj * 4;
            *(float4*)(hn + off)  = v;
            *(float4*)(agg + off) = v;
        }
    }
}

// ---------------------------------------------------------------------------
// Edge scatter: agg[dst] += hn[src]  (no per-edge multiply after refactor).
// 16 threads per edge, one float4 + red.add.v4 per thread.
// ---------------------------------------------------------------------------
__device__ __forceinline__ void red_add_v4(float* addr, float4 v) {
    asm volatile("red.global.add.v4.f32 [%0], {%1, %2, %3, %4};"
                 :: "l"(addr), "f"(v.x), "f"(v.y), "f"(v.z), "f"(v.w)
                 : "memory");
}

__global__ void __launch_bounds__(256)
k_scatter(const int* __restrict__ src, const int* __restrict__ dst,
          const float* __restrict__ hn, float* __restrict__ agg, int E) {
    int gid = blockIdx.x * blockDim.x + threadIdx.x;
    int e = gid >> 4;
    int j = gid & 15;
    if (e >= E) return;
    int s = __ldg(&src[e]);
    int d = __ldg(&dst[e]);
    float4 v = *(const float4*)(hn + (size_t)s * 64 + j * 4);
    red_add_v4(agg + (size_t)d * 64 + j * 4, v);
}

// ---------------------------------------------------------------------------
// Pointwise epilogues
// ---------------------------------------------------------------------------
__global__ void k_relu_bias(const float* __restrict__ agg,
                            const float* __restrict__ dinv,
                            const float* __restrict__ b,
                            float* __restrict__ out, int total) {
    int idx = blockIdx.x * blockDim.x + threadIdx.x;
    if (idx >= total) return;
    int i = idx >> 6;
    int c = idx & 63;
    float v = dinv[i] * agg[idx] + __ldg(&b[c]);
    out[idx] = v > 0.0f ? v : 0.0f;
}

__global__ void k_final_bias(const float* __restrict__ dinv,
                             const float* __restrict__ b,
                             float* __restrict__ out, int total) {
    int idx = blockIdx.x * blockDim.x + threadIdx.x;
    if (idx >= total) return;
    int i = idx >> 6;
    int c = idx & 63;
    out[idx] = dinv[i] * out[idx] + __ldg(&b[c]);
}

// ---------------------------------------------------------------------------
// Launch
// ---------------------------------------------------------------------------
extern "C" void kernel_launch(void* const* d_in, const int* in_sizes, int n_in,
                              void* d_out, int out_size) {
    const float* x  = (const float*)d_in[0];
    const int*   ei = (const int*)d_in[1];
    const float* W1 = (const float*)d_in[2];
    const float* b1 = (const float*)d_in[3];
    const float* W2 = (const float*)d_in[4];
    const float* b2 = (const float*)d_in[5];

    const int E = in_sizes[1] / 2;
    const int M = out_size / HID;   // 50000
    const int* src = ei;
    const int* dst = ei + E;

    float *deg, *bufA, *bufB;
    cudaGetSymbolAddress((void**)&deg,  g_deg);
    cudaGetSymbolAddress((void**)&bufA, g_bufA);
    cudaGetSymbolAddress((void**)&bufB, g_bufB);
    float* out = (float*)d_out;

    // 1. degree + symmetric norm
    k_init_deg<<<(M + 255) / 256, 256>>>(deg, M);
    k_accum_deg<<<(E + 255) / 256, 256>>>(dst, deg, E);
    k_rsqrt<<<(M + 255) / 256, 256>>>(deg, M);

    // 2. layer 1: hn1 = (x@W1)*dinv  -> bufA, agg1 init -> bufB
    k_gemm_hn<IN_DIM><<<(M + 127) / 128, 128>>>(x, W1, deg, bufA, bufB, M);
    // 3. scatter: agg1[dst] += hn1[src]
    {
        long long tot = (long long)E * 16;
        k_scatter<<<(int)((tot + 255) / 256), 256>>>(src, dst, bufA, bufB, E);
    }
    // 4. h2 = relu(dinv*agg1 + b1) -> bufA
    k_relu_bias<<<(M * HID + 255) / 256, 256>>>(bufB, deg, b1, bufA, M * HID);

    // 5. layer 2: hn2 = (h2@W2)*dinv -> bufB, agg2 init -> out
    k_gemm_hn<HID><<<(M + 127) / 128, 128>>>(bufA, W2, deg, bufB, out, M);
    // 6. scatter: out[dst] += hn2[src]
    {
        long long tot = (long long)E * 16;
        k_scatter<<<(int)((tot + 255) / 256), 256>>>(src, dst, bufB, out, E);
    }
    // 7. out = dinv*out + b2
    k_final_bias<<<(M * HID + 255) / 256, 256>>>(deg, b2, out, M * HID);
}

// round 2
// speedup vs baseline: 1.3756x; 1.3756x over previous
#include <cuda_runtime.h>
#include <cstdint>
#include <cstddef>

#define NUM_NODES 50000
#define HID 64
#define IN_DIM 512

// Scratch (no allocation allowed -> __device__ globals)
__device__ float g_deg[NUM_NODES];
__device__ float g_bufA[NUM_NODES * HID];
__device__ float g_bufB[NUM_NODES * HID];

// ---------------------------------------------------------------------------
// degree / normalization
// ---------------------------------------------------------------------------
__global__ void k_init_deg(float* deg, int n) {
    int i = blockIdx.x * blockDim.x + threadIdx.x;
    if (i < n) deg[i] = 1.0f;  // self-loop
}

__global__ void k_accum_deg(const int* __restrict__ dst, float* deg, int E) {
    int e = blockIdx.x * blockDim.x + threadIdx.x;
    if (e < E) atomicAdd(&deg[dst[e]], 1.0f);
}

__global__ void k_rsqrt(float* deg, int n) {
    int i = blockIdx.x * blockDim.x + threadIdx.x;
    if (i < n) deg[i] = rsqrtf(deg[i]);
}

// ---------------------------------------------------------------------------
// tf32 tensor-core GEMM with epilogue:
//   hn[row] = (X @ W)[row] * dinv[row];  agg init = hn (self-loop term).
// BM=128, BN=64(full), BK=16. 256 threads = 8 warps (4M x 2N).
// Each warp: 32x32 via 2(m16) x 4(n8) mma.sync.m16n8k8.tf32 tiles.
// Smem padded for conflict-free fragment LDS (A stride 20, B stride 72).
// ---------------------------------------------------------------------------
#define BM 128
#define PADA 20
#define PADB 72

__device__ __forceinline__ float to_tf32(float x) {
    uint32_t r;
    asm("cvt.rna.tf32.f32 %0, %1;" : "=r"(r) : "f"(x));
    return __uint_as_float(r);
}

template <int K>
__global__ void __launch_bounds__(256)
k_gemm_tc(const float* __restrict__ X, const float* __restrict__ W,
          const float* __restrict__ dinv,
          float* __restrict__ hn, float* __restrict__ agg, int M) {
    __shared__ float as[BM * PADA];   // as[row*PADA + k]   (tf32 bits)
    __shared__ float ws[16 * PADB];   // ws[k*PADB + n]     (tf32 bits)

    const int t    = threadIdx.x;
    const int m0   = blockIdx.x * BM;
    const int lane = t & 31;
    const int wid  = t >> 5;
    const int wm   = wid >> 1;       // 0..3
    const int wn   = wid & 1;        // 0..1
    const int g    = lane >> 2;      // groupID 0..7
    const int tig  = lane & 3;       // thread-in-group

    // A global-load mapping: 2 float4 per thread, row = t>>1
    const int arow = t >> 1;
    const int ac0  = (t & 1) * 8;
    // B global-load mapping: 1 float4 per thread
    const int brow = t >> 4;
    const int bc   = (t & 15) * 4;

    float c[2][4][4];
#pragma unroll
    for (int mt = 0; mt < 2; mt++)
#pragma unroll
        for (int nt = 0; nt < 4; nt++)
#pragma unroll
            for (int i = 0; i < 4; i++) c[mt][nt][i] = 0.0f;

    for (int k0 = 0; k0 < K; k0 += 16) {
        // ---- load + convert A tile (128x16)
        {
            bool ok = (m0 + arow) < M;
            const float* p = X + (size_t)(m0 + arow) * K + k0 + ac0;
#pragma unroll
            for (int h = 0; h < 2; h++) {
                float4 v = make_float4(0.f, 0.f, 0.f, 0.f);
                if (ok) v = *(const float4*)(p + h * 4);
                float* d = &as[arow * PADA + ac0 + h * 4];
                d[0] = to_tf32(v.x); d[1] = to_tf32(v.y);
                d[2] = to_tf32(v.z); d[3] = to_tf32(v.w);
            }
        }
        // ---- load + convert B tile (16x64)
        {
            float4 v = *(const float4*)(W + (size_t)(k0 + brow) * 64 + bc);
            float* d = &ws[brow * PADB + bc];
            d[0] = to_tf32(v.x); d[1] = to_tf32(v.y);
            d[2] = to_tf32(v.z); d[3] = to_tf32(v.w);
        }
        __syncthreads();

#pragma unroll
        for (int ks = 0; ks < 16; ks += 8) {
            uint32_t a[2][4], b[4][2];
#pragma unroll
            for (int mt = 0; mt < 2; mt++) {
                int r = wm * 32 + mt * 16 + g;
                a[mt][0] = __float_as_uint(as[r * PADA + ks + tig]);
                a[mt][1] = __float_as_uint(as[(r + 8) * PADA + ks + tig]);
                a[mt][2] = __float_as_uint(as[r * PADA + ks + tig + 4]);
                a[mt][3] = __float_as_uint(as[(r + 8) * PADA + ks + tig + 4]);
            }
#pragma unroll
            for (int nt = 0; nt < 4; nt++) {
                int n = wn * 32 + nt * 8 + g;
                b[nt][0] = __float_as_uint(ws[(ks + tig) * PADB + n]);
                b[nt][1] = __float_as_uint(ws[(ks + tig + 4) * PADB + n]);
            }
#pragma unroll
            for (int mt = 0; mt < 2; mt++)
#pragma unroll
                for (int nt = 0; nt < 4; nt++) {
                    asm volatile(
                        "mma.sync.aligned.m16n8k8.row.col.f32.tf32.tf32.f32 "
                        "{%0,%1,%2,%3}, {%4,%5,%6,%7}, {%8,%9}, {%0,%1,%2,%3};"
                        : "+f"(c[mt][nt][0]), "+f"(c[mt][nt][1]),
                          "+f"(c[mt][nt][2]), "+f"(c[mt][nt][3])
                        : "r"(a[mt][0]), "r"(a[mt][1]), "r"(a[mt][2]), "r"(a[mt][3]),
                          "r"(b[nt][0]), "r"(b[nt][1]));
                }
        }
        __syncthreads();
    }

    // ---- epilogue: scale by dinv[row], write hn and agg
#pragma unroll
    for (int mt = 0; mt < 2; mt++) {
        int rbase = m0 + wm * 32 + mt * 16 + g;
#pragma unroll
        for (int half = 0; half < 2; half++) {
            int row = rbase + half * 8;
            if (row < M) {
                float s = dinv[row];
#pragma unroll
                for (int nt = 0; nt < 4; nt++) {
                    float2 v;
                    v.x = c[mt][nt][half * 2 + 0] * s;
                    v.y = c[mt][nt][half * 2 + 1] * s;
                    size_t off = (size_t)row * 64 + wn * 32 + nt * 8 + 2 * tig;
                    *(float2*)(hn + off)  = v;
                    *(float2*)(agg + off) = v;
                }
            }
        }
    }
}

// ---------------------------------------------------------------------------
// Edge scatter: agg[dst] += hn[src].  16 threads/edge, red.add.v4 per thread.
// ---------------------------------------------------------------------------
__device__ __forceinline__ void red_add_v4(float* addr, float4 v) {
    asm volatile("red.global.add.v4.f32 [%0], {%1, %2, %3, %4};"
                 :: "l"(addr), "f"(v.x), "f"(v.y), "f"(v.z), "f"(v.w)
                 : "memory");
}

__global__ void __launch_bounds__(256)
k_scatter(const int* __restrict__ src, const int* __restrict__ dst,
          const float* __restrict__ hn, float* __restrict__ agg, int E) {
    int gid = blockIdx.x * blockDim.x + threadIdx.x;
    int e = gid >> 4;
    int j = gid & 15;
    if (e >= E) return;
    int s = __ldg(&src[e]);
    int d = __ldg(&dst[e]);
    float4 v = *(const float4*)(hn + (size_t)s * 64 + j * 4);
    red_add_v4(agg + (size_t)d * 64 + j * 4, v);
}

// ---------------------------------------------------------------------------
// Pointwise epilogues
// ---------------------------------------------------------------------------
__global__ void k_relu_bias(const float* __restrict__ agg,
                            const float* __restrict__ dinv,
                            const float* __restrict__ b,
                            float* __restrict__ out, int total) {
    int idx = blockIdx.x * blockDim.x + threadIdx.x;
    if (idx >= total) return;
    int i = idx >> 6;
    int c = idx & 63;
    float v = dinv[i] * agg[idx] + __ldg(&b[c]);
    out[idx] = v > 0.0f ? v : 0.0f;
}

__global__ void k_final_bias(const float* __restrict__ dinv,
                             const float* __restrict__ b,
                             float* __restrict__ out, int total) {
    int idx = blockIdx.x * blockDim.x + threadIdx.x;
    if (idx >= total) return;
    int i = idx >> 6;
    int c = idx & 63;
    out[idx] = dinv[i] * out[idx] + __ldg(&b[c]);
}

// ---------------------------------------------------------------------------
// Launch
// ---------------------------------------------------------------------------
extern "C" void kernel_launch(void* const* d_in, const int* in_sizes, int n_in,
                              void* d_out, int out_size) {
    const float* x  = (const float*)d_in[0];
    const int*   ei = (const int*)d_in[1];
    const float* W1 = (const float*)d_in[2];
    const float* b1 = (const float*)d_in[3];
    const float* W2 = (const float*)d_in[4];
    const float* b2 = (const float*)d_in[5];

    const int E = in_sizes[1] / 2;
    const int M = out_size / HID;
    const int* src = ei;
    const int* dst = ei + E;

    float *deg, *bufA, *bufB;
    cudaGetSymbolAddress((void**)&deg,  g_deg);
    cudaGetSymbolAddress((void**)&bufA, g_bufA);
    cudaGetSymbolAddress((void**)&bufB, g_bufB);
    float* out = (float*)d_out;

    // 1. degree + symmetric norm
    k_init_deg<<<(M + 255) / 256, 256>>>(deg, M);
    k_accum_deg<<<(E + 255) / 256, 256>>>(dst, deg, E);
    k_rsqrt<<<(M + 255) / 256, 256>>>(deg, M);

    const int gblk = (M + BM - 1) / BM;

    // 2. layer 1: hn1 = (x@W1)*dinv -> bufA, agg1 init -> bufB
    k_gemm_tc<IN_DIM><<<gblk, 256>>>(x, W1, deg, bufA, bufB, M);
    // 3. scatter: agg1[dst] += hn1[src]
    {
        long long tot = (long long)E * 16;
        k_scatter<<<(int)((tot + 255) / 256), 256>>>(src, dst, bufA, bufB, E);
    }
    // 4. h2 = relu(dinv*agg1 + b1) -> bufA
    k_relu_bias<<<(M * HID + 255) / 256, 256>>>(bufB, deg, b1, bufA, M * HID);

    // 5. layer 2: hn2 = (h2@W2)*dinv -> bufB, agg2 init -> out
    k_gemm_tc<HID><<<gblk, 256>>>(bufA, W2, deg, bufB, out, M);
    // 6. scatter: out[dst] += hn2[src]
    {
        long long tot = (long long)E * 16;
        k_scatter<<<(int)((tot + 255) / 256), 256>>>(src, dst, bufB, out, E);
    }
    // 7. out = dinv*out + b2
    k_final_bias<<<(M * HID + 255) / 256, 256>>>(deg, b2, out, M * HID);
}